// round 1
// baseline (speedup 1.0000x reference)
#include <cuda_runtime.h>
#include <math.h>

#define DSZ 128
#define D3 (DSZ*DSZ*DSZ)
#define TSX 32
#define TSY 4
#define TSZ 4
#define HX 36
#define HY 8
#define HZ 8
#define HTOT (HX*HY*HZ)   // 2304 halo cells
#define SMEM_BYTES (6*HTOT*4)

__global__ __launch_bounds__(512, 2)
void dem_step(const float* __restrict__ X,  const float* __restrict__ Y,  const float* __restrict__ Z,
              const float* __restrict__ VX, const float* __restrict__ VY, const float* __restrict__ VZ,
              const float* __restrict__ MK, float* __restrict__ out, float ETAc)
{
    extern __shared__ float sm[];
    float* sx  = sm;
    float* sy  = sm + 1*HTOT;
    float* sz  = sm + 2*HTOT;
    float* svx = sm + 3*HTOT;
    float* svy = sm + 4*HTOT;
    float* svz = sm + 5*HTOT;

    const int tx = threadIdx.x, ty = threadIdx.y, tz = threadIdx.z;
    const int x0 = blockIdx.x * TSX, y0 = blockIdx.y * TSY, z0 = blockIdx.z * TSZ;
    const int tid = (tz * TSY + ty) * TSX + tx;

    // ---- cooperative halo load (out-of-range == empty == 0, exact per roll analysis) ----
    for (int idx = tid; idx < HTOT; idx += TSX * TSY * TSZ) {
        int lx = idx % HX;
        int t  = idx / HX;
        int ly = t & (HY - 1);
        int lz = t >> 3;
        int gx = x0 + lx - 2, gy = y0 + ly - 2, gz = z0 + lz - 2;
        if ((unsigned)gx < DSZ && (unsigned)gy < DSZ && (unsigned)gz < DSZ) {
            int g = (gz * DSZ + gy) * DSZ + gx;
            sx[idx]  = X[g];  sy[idx]  = Y[g];  sz[idx]  = Z[g];
            svx[idx] = VX[g]; svy[idx] = VY[g]; svz[idx] = VZ[g];
        } else {
            sx[idx]  = 0.f; sy[idx]  = 0.f; sz[idx]  = 0.f;
            svx[idx] = 0.f; svy[idx] = 0.f; svz[idx] = 0.f;
        }
    }
    __syncthreads();

    const int cx = tx + 2, cy = ty + 2, cz = tz + 2;
    const int cofs = (cz * HY + cy) * HX + cx;
    const float px  = sx[cofs],  py  = sy[cofs],  pz  = sz[cofs];
    const float pvx = svx[cofs], pvy = svy[cofs], pvz = svz[cofs];

    float fx = 0.f, fy = 0.f, fz = 0.f;

    auto body = [&](int off) {
        float dx = px - sx[off];
        float dy = py - sy[off];
        float dz = pz - sz[off];
        float sq = fmaf(dx, dx, fmaf(dy, dy, fmaf(dz, dz, 1e-20f)));
        float rs;
        asm("rsqrt.approx.f32 %0, %1;" : "=f"(rs) : "f"(sq));
        float dist = sq * rs;                       // == sqrt(sq)
        float inv  = (dist > 1e-4f) ? rs : 1e4f;    // 1 / clamp(dist, 1e-4)
        float dvx = pvx - svx[off];
        float dvy = pvy - svy[off];
        float dvz = pvz - svz[off];
        float dot = fmaf(dvx, dx, fmaf(dvy, dy, dvz * dz));
        float coef = fmaf(500000.f, dist - 2.0f, ETAc * dot * inv) * inv;
        coef = (dist < 2.0f) ? coef : 0.f;
        fx = fmaf(coef, dx, fx);
        fy = fmaf(coef, dy, fy);
        fz = fmaf(coef, dz, fz);
    };

    // ---- 81 NEAR shifts (at most one |o_i|==2): all other shifts provably contribute 0
    //      for occupied-occupied pairs; empty-neighbor far terms handled below. ----
    #pragma unroll
    for (int oz = -2; oz <= 2; ++oz) {
        #pragma unroll
        for (int oy = -2; oy <= 2; ++oy) {
            const int n2 = ((oz * oz == 4) ? 1 : 0) + ((oy * oy == 4) ? 1 : 0);
            if (n2 == 2) continue;
            const int ro = ((cz + oz) * HY + (cy + oy)) * HX + cx;
            if (n2 == 0) { body(ro - 2); body(ro - 1); body(ro); body(ro + 1); body(ro + 2); }
            else         { body(ro - 1); body(ro); body(ro + 1); }
        }
    }

    const int ggx = x0 + tx, ggy = y0 + ty, ggz = z0 + tz;
    const float m = MK[(ggz * DSZ + ggy) * DSZ + ggx];

    // ---- corner correction: far-shift contributions exist only via empty neighbors,
    //      nonzero only when |p| < 2 (origin-corner cells). Exceedingly rare branch. ----
    float p2 = fmaf(px, px, fmaf(py, py, pz * pz));
    if (m != 0.f && p2 < 4.f) {
        int cnt = 0;
        for (int oz = -2; oz <= 2; ++oz)
            for (int oy = -2; oy <= 2; ++oy)
                for (int ox = -2; ox <= 2; ++ox) {
                    int nf = (oz * oz == 4) + (oy * oy == 4) + (ox * ox == 4);
                    if (nf >= 2 && sx[((cz + oz) * HY + (cy + oy)) * HX + (cx + ox)] == 0.f)
                        cnt++;
                }
        float sq = p2 + 1e-20f;
        float rs;
        asm("rsqrt.approx.f32 %0, %1;" : "=f"(rs) : "f"(sq));
        float dist = sq * rs;
        float inv  = (dist > 1e-4f) ? rs : 1e4f;
        float dot  = fmaf(pvx, px, fmaf(pvy, py, pvz * pz));
        float coef = fmaf(500000.f, dist - 2.0f, ETAc * dot * inv) * inv;
        if (dist < 2.0f) {
            float c = coef * (float)cnt;
            fx = fmaf(c, px, fx);
            fy = fmaf(c, py, fy);
            fz = fmaf(c, pz, fz);
        }
    }

    // ---- boundary overlap forces ----
    float bl = (px != 0.f && px < 1.0f)   ? 1.f : 0.f;
    float br = (px > 126.0f)              ? 1.f : 0.f;
    float bb = (py != 0.f && py < 1.0f)   ? 1.f : 0.f;
    float bt = (py > 126.0f)              ? 1.f : 0.f;
    float bf = (pz != 0.f && pz < 1.0f)   ? 1.f : 0.f;
    float bk = (pz > 126.0f)              ? 1.f : 0.f;
    float fxb = 500000.f * bl * m * (1.0f - px) - 500000.f * br * m * (px - 126.0f)
              - ETAc * pvx * bl * m - ETAc * pvx * br * m;
    float fyb = 500000.f * bb * m * (1.0f - py) - 500000.f * bt * m * (py - 126.0f)
              - ETAc * pvy * bb * m - ETAc * pvy * bt * m;
    float fzb = 500000.f * bf * m * (1.0f - pz) - 500000.f * bk * m * (pz - 126.0f)
              - ETAc * pvz * bf * m - ETAc * pvz * bk * m;

    // ---- integrate ----
    float vxn = pvx + 1e-4f * m * (-fx + fxb);
    float vyn = pvy + 1e-4f * m * (-9.8f - fy + fyb);
    float vzn = pvz + 1e-4f * m * (-fz + fzb);
    float xn = fmaf(1e-4f, vxn, px);
    float yn = fmaf(1e-4f, vyn, py);
    float zn = fmaf(1e-4f, vzn, pz);

    // ---- cell-list relocation: base is all-zero (memset); scatter new state to new cell ----
    int c0x = __float2int_rn(px), c0y = __float2int_rn(py), c0z = __float2int_rn(pz);
    bool lov = (c0x != 0) && (c0y != 0) && (c0z != 0);
    int c1x = __float2int_rn(xn), c1y = __float2int_rn(yn), c1z = __float2int_rn(zn);
    bool lnv = (c1x != 0) && (c1y != 0) && (c1z != 0)
            && (unsigned)c1x < DSZ && (unsigned)c1y < DSZ && (unsigned)c1z < DSZ;
    if (lnv) {
        int ln = (c1z * DSZ + c1y) * DSZ + c1x;
        out[0 * D3 + ln] = lov ? xn  : 0.f;
        out[1 * D3 + ln] = lov ? yn  : 0.f;
        out[2 * D3 + ln] = lov ? zn  : 0.f;
        out[3 * D3 + ln] = lov ? vxn : 0.f;
        out[4 * D3 + ln] = lov ? vyn : 0.f;
        out[5 * D3 + ln] = lov ? vzn : 0.f;
        out[6 * D3 + ln] = 1.0f;
    }
}

extern "C" void kernel_launch(void* const* d_in, const int* in_sizes, int n_in,
                              void* d_out, int out_size)
{
    const float* X  = (const float*)d_in[0];
    const float* Y  = (const float*)d_in[1];
    const float* Z  = (const float*)d_in[2];
    const float* VX = (const float*)d_in[3];
    const float* VY = (const float*)d_in[4];
    const float* VZ = (const float*)d_in[5];
    const float* MK = (const float*)d_in[6];
    float* out = (float*)d_out;

    // base state: everything zero (new fields are exactly 0 at empty cells;
    // all occupied cells appear in `lo`, hence are zeroed by .at[lo].set(0)).
    cudaMemsetAsync(out, 0, (size_t)out_size * sizeof(float));

    double alpha = -log(0.7) / M_PI;
    double gamma = alpha / sqrt(alpha * alpha + 1.0);
    float eta = (float)(2.0 * gamma * sqrt(500000.0 * 1.0));

    cudaFuncSetAttribute(dem_step, cudaFuncAttributeMaxDynamicSharedMemorySize, SMEM_BYTES);

    dim3 grid(DSZ / TSX, DSZ / TSY, DSZ / TSZ);
    dim3 block(TSX, TSY, TSZ);
    dem_step<<<grid, block, SMEM_BYTES>>>(X, Y, Z, VX, VY, VZ, MK, out, eta);
}

// round 2
// speedup vs baseline: 1.1618x; 1.1618x over previous
#include <cuda_runtime.h>
#include <math.h>

#define DSZ 128
#define D3 (DSZ*DSZ*DSZ)
#define TSX 32
#define TSY 4
#define TSZ 4
#define HX 36
#define HY 8
#define HZ 8
#define HTOT (HX*HY*HZ)   // 2304 halo cells
#define SMEM_BYTES (3*HTOT*8)   // three float2 arrays

__global__ __launch_bounds__(512, 3)
void dem_step(const float* __restrict__ X,  const float* __restrict__ Y,  const float* __restrict__ Z,
              const float* __restrict__ VX, const float* __restrict__ VY, const float* __restrict__ VZ,
              const float* __restrict__ MK, float* __restrict__ out, float ETAc)
{
    extern __shared__ float2 sm2[];
    float2* sxy   = sm2;            // (x, y)
    float2* szvx  = sm2 + HTOT;     // (z, vx)
    float2* svyvz = sm2 + 2*HTOT;   // (vy, vz)

    const int tx = threadIdx.x, ty = threadIdx.y, tz = threadIdx.z;
    const int x0 = blockIdx.x * TSX, y0 = blockIdx.y * TSY, z0 = blockIdx.z * TSZ;
    const int tid = (tz * TSY + ty) * TSX + tx;

    // ---- cooperative halo load (out-of-range == empty == 0, exact per roll analysis) ----
    for (int idx = tid; idx < HTOT; idx += TSX * TSY * TSZ) {
        int lx = idx % HX;
        int t  = idx / HX;
        int ly = t & (HY - 1);
        int lz = t >> 3;
        int gx = x0 + lx - 2, gy = y0 + ly - 2, gz = z0 + lz - 2;
        float vx_ = 0.f, vy_ = 0.f, vz_ = 0.f, xx = 0.f, yy = 0.f, zz = 0.f;
        if ((unsigned)gx < DSZ && (unsigned)gy < DSZ && (unsigned)gz < DSZ) {
            int g = (gz * DSZ + gy) * DSZ + gx;
            xx = X[g]; yy = Y[g]; zz = Z[g];
            vx_ = VX[g]; vy_ = VY[g]; vz_ = VZ[g];
        }
        sxy[idx]   = make_float2(xx, yy);
        szvx[idx]  = make_float2(zz, vx_);
        svyvz[idx] = make_float2(vy_, vz_);
    }
    __syncthreads();

    const int cx = tx + 2, cy = ty + 2, cz = tz + 2;
    const int cofs = (cz * HY + cy) * HX + cx;
    const float2 pxy = sxy[cofs], pzvx = szvx[cofs], pvyvz = svyvz[cofs];
    const float px = pxy.x,   py = pxy.y,    pz = pzvx.x;
    const float pvx = pzvx.y, pvy = pvyvz.x, pvz = pvyvz.y;

    float fx = 0.f, fy = 0.f, fz = 0.f;

    auto body = [&](int off) {
        float2 qxy = sxy[off];
        float2 qzvx = szvx[off];
        float2 qvv = svyvz[off];
        float dx = px - qxy.x;
        float dy = py - qxy.y;
        float dz = pz - qzvx.x;
        float sq = fmaf(dx, dx, fmaf(dy, dy, fmaf(dz, dz, 1e-20f)));
        float rs;
        asm("rsqrt.approx.f32 %0, %1;" : "=f"(rs) : "f"(sq));
        float dist = sq * rs;                 // == sqrt(sq); rs finite (sq >= 1e-20)
        float dvx = pvx - qzvx.y;
        float dvy = pvy - qvv.x;
        float dvz = pvz - qvv.y;
        float dot = fmaf(dvx, dx, fmaf(dvy, dy, dvz * dz));
        // (KN*(dist-2) + ETA*dot*rs) * rs   — clamp(dist,1e-4) provably never binds
        float coef = fmaf(500000.f, dist - 2.0f, ETAc * dot * rs) * rs;
        coef = (dist < 2.0f) ? coef : 0.f;
        fx = fmaf(coef, dx, fx);
        fy = fmaf(coef, dy, fy);
        fz = fmaf(coef, dz, fz);
    };

    // ---- 81 NEAR shifts (at most one |o_i|==2): other shifts contribute exactly 0
    //      for occupied-occupied pairs; empty-neighbor far terms handled below. ----
    #pragma unroll
    for (int oz = -2; oz <= 2; ++oz) {
        #pragma unroll
        for (int oy = -2; oy <= 2; ++oy) {
            const int n2 = ((oz * oz == 4) ? 1 : 0) + ((oy * oy == 4) ? 1 : 0);
            if (n2 == 2) continue;
            const int ro = ((cz + oz) * HY + (cy + oy)) * HX + cx;
            if (n2 == 0) { body(ro - 2); body(ro - 1); body(ro); body(ro + 1); body(ro + 2); }
            else         { body(ro - 1); body(ro); body(ro + 1); }
        }
    }

    const int ggx = x0 + tx, ggy = y0 + ty, ggz = z0 + tz;
    const float m = MK[(ggz * DSZ + ggy) * DSZ + ggx];

    // ---- corner correction: far-shift contributions exist only via empty neighbors,
    //      nonzero only when |p| < 2 (origin-corner cells). Exceedingly rare branch. ----
    float p2 = fmaf(px, px, fmaf(py, py, pz * pz));
    if (m != 0.f && p2 < 4.f) {
        int cnt = 0;
        for (int oz = -2; oz <= 2; ++oz)
            for (int oy = -2; oy <= 2; ++oy)
                for (int ox = -2; ox <= 2; ++ox) {
                    int nf = (oz * oz == 4) + (oy * oy == 4) + (ox * ox == 4);
                    if (nf >= 2 && sxy[((cz + oz) * HY + (cy + oy)) * HX + (cx + ox)].x == 0.f)
                        cnt++;
                }
        float sq = p2 + 1e-20f;
        float rs;
        asm("rsqrt.approx.f32 %0, %1;" : "=f"(rs) : "f"(sq));
        float dist = sq * rs;
        float inv  = (dist > 1e-4f) ? rs : 1e4f;
        float dot  = fmaf(pvx, px, fmaf(pvy, py, pvz * pz));
        float coef = fmaf(500000.f, dist - 2.0f, ETAc * dot * inv) * inv;
        if (dist < 2.0f) {
            float c = coef * (float)cnt;
            fx = fmaf(c, px, fx);
            fy = fmaf(c, py, fy);
            fz = fmaf(c, pz, fz);
        }
    }

    // ---- boundary overlap forces ----
    float bl = (px != 0.f && px < 1.0f)   ? 1.f : 0.f;
    float br = (px > 126.0f)              ? 1.f : 0.f;
    float bb = (py != 0.f && py < 1.0f)   ? 1.f : 0.f;
    float bt = (py > 126.0f)              ? 1.f : 0.f;
    float bf = (pz != 0.f && pz < 1.0f)   ? 1.f : 0.f;
    float bk = (pz > 126.0f)              ? 1.f : 0.f;
    float fxb = 500000.f * bl * m * (1.0f - px) - 500000.f * br * m * (px - 126.0f)
              - ETAc * pvx * bl * m - ETAc * pvx * br * m;
    float fyb = 500000.f * bb * m * (1.0f - py) - 500000.f * bt * m * (py - 126.0f)
              - ETAc * pvy * bb * m - ETAc * pvy * bt * m;
    float fzb = 500000.f * bf * m * (1.0f - pz) - 500000.f * bk * m * (pz - 126.0f)
              - ETAc * pvz * bf * m - ETAc * pvz * bk * m;

    // ---- integrate ----
    float vxn = pvx + 1e-4f * m * (-fx + fxb);
    float vyn = pvy + 1e-4f * m * (-9.8f - fy + fyb);
    float vzn = pvz + 1e-4f * m * (-fz + fzb);
    float xn = fmaf(1e-4f, vxn, px);
    float yn = fmaf(1e-4f, vyn, py);
    float zn = fmaf(1e-4f, vzn, pz);

    // ---- cell-list relocation: base is all-zero (memset); scatter new state to new cell ----
    int c0x = __float2int_rn(px), c0y = __float2int_rn(py), c0z = __float2int_rn(pz);
    bool lov = (c0x != 0) && (c0y != 0) && (c0z != 0);
    int c1x = __float2int_rn(xn), c1y = __float2int_rn(yn), c1z = __float2int_rn(zn);
    bool lnv = (c1x != 0) && (c1y != 0) && (c1z != 0)
            && (unsigned)c1x < DSZ && (unsigned)c1y < DSZ && (unsigned)c1z < DSZ;
    if (lnv) {
        int ln = (c1z * DSZ + c1y) * DSZ + c1x;
        out[0 * D3 + ln] = lov ? xn  : 0.f;
        out[1 * D3 + ln] = lov ? yn  : 0.f;
        out[2 * D3 + ln] = lov ? zn  : 0.f;
        out[3 * D3 + ln] = lov ? vxn : 0.f;
        out[4 * D3 + ln] = lov ? vyn : 0.f;
        out[5 * D3 + ln] = lov ? vzn : 0.f;
        out[6 * D3 + ln] = 1.0f;
    }
}

extern "C" void kernel_launch(void* const* d_in, const int* in_sizes, int n_in,
                              void* d_out, int out_size)
{
    const float* X  = (const float*)d_in[0];
    const float* Y  = (const float*)d_in[1];
    const float* Z  = (const float*)d_in[2];
    const float* VX = (const float*)d_in[3];
    const float* VY = (const float*)d_in[4];
    const float* VZ = (const float*)d_in[5];
    const float* MK = (const float*)d_in[6];
    float* out = (float*)d_out;

    // base state: everything zero (new fields are exactly 0 at empty cells;
    // all occupied cells appear in `lo`, hence are zeroed by .at[lo].set(0)).
    cudaMemsetAsync(out, 0, (size_t)out_size * sizeof(float));

    double alpha = -log(0.7) / M_PI;
    double gamma = alpha / sqrt(alpha * alpha + 1.0);
    float eta = (float)(2.0 * gamma * sqrt(500000.0 * 1.0));

    cudaFuncSetAttribute(dem_step, cudaFuncAttributeMaxDynamicSharedMemorySize, SMEM_BYTES);

    dim3 grid(DSZ / TSX, DSZ / TSY, DSZ / TSZ);
    dim3 block(TSX, TSY, TSZ);
    dem_step<<<grid, block, SMEM_BYTES>>>(X, Y, Z, VX, VY, VZ, MK, out, eta);
}